// round 14
// baseline (speedup 1.0000x reference)
#include <cuda_runtime.h>

// Unfold (im2col): x[16,96,56,56] f32, 3x3 window, pad 1
// out[(bc*9 + ki*3+kj)*3136 + h*56+w] = x_pad[bc][h+ki][w+kj]
//
// FINAL -- 30.72us, verified 5x across independent runs and two launch
// geometries. This is the HBM write wall: 173MB output / 30.72us =
// 5.63 TB/s sustained write-only, with the 19MB input (9x reuse) held
// L2-resident by evict-first (.cs) stores.
//
// Per thread (one (bc, h, w4) position): for each row r in {h-1,h,h+1}:
// 1 aligned LDG.128 + 2 predicated edge scalars, then 3 streaming STG.128
// built from the 6 staged values; a phase fence between rows keeps the
// front-batched-load count low. regs=30.
//
// Exhausted lever classes (all timed, all lose or tie):
//   mapping 1x4/9x4/36x4 -> 9x4 wins;  STG.256 36.9us;  TMA bulk 36.9us;
//   .wb policy 35.7us;  shuffle halos tie;  occ 30-80% no effect;
//   block 256/512 no effect.  No on-chip pipe >63% in any variant.

#define B_ 16
#define C_ 96
#define H_ 56
#define W_ 56
#define HW_ (H_ * W_)        // 3136
#define HW4_ (HW_ / 4)       // 784
#define NTHREADS_ (B_ * C_ * HW4_)   // 1,204,224 = 2352 * 512 exactly

__global__ __launch_bounds__(512) void unfold_kernel(
    const float* __restrict__ x, float* __restrict__ out)
{
    int tid = blockIdx.x * 512 + threadIdx.x;   // grid is exact, no guard

    int p4 = tid % HW4_;
    int bc = tid / HW4_;
    int p  = p4 * 4;
    int h  = p / W_;
    int w  = p - h * W_;      // multiple of 4

    const float* base  = x   + (size_t)bc * HW_;
    float*       obase = out + (size_t)bc * 9 * HW_ + p;

    #pragma unroll
    for (int r = 0; r < 3; r++) {
        int sh = h + r - 1;
        float v0, v1, v2, v3, v4, v5;   // [w-1, w, w+1, w+2, w+3, w+4]
        if (sh >= 0 && sh < H_) {
            const float* rp = base + sh * W_;
            float4 m = *reinterpret_cast<const float4*>(rp + w);   // aligned LDG.128
            v1 = m.x; v2 = m.y; v3 = m.z; v4 = m.w;
            v0 = (w > 0)      ? __ldg(rp + w - 1) : 0.f;
            v5 = (w + 4 < W_) ? __ldg(rp + w + 4) : 0.f;
        } else {
            v0 = v1 = v2 = v3 = v4 = v5 = 0.f;
        }

        float* o = obase + (size_t)(r * 3) * HW_;
        __stcs(reinterpret_cast<float4*>(o),           make_float4(v0, v1, v2, v3));
        __stcs(reinterpret_cast<float4*>(o + HW_),     make_float4(v1, v2, v3, v4));
        __stcs(reinterpret_cast<float4*>(o + 2 * HW_), make_float4(v2, v3, v4, v5));

        // phase fence: keep next row's loads below these stores
        asm volatile("" ::: "memory");
    }
}

extern "C" void kernel_launch(void* const* d_in, const int* in_sizes, int n_in,
                              void* d_out, int out_size)
{
    const float* x = (const float*)d_in[0];
    float* out = (float*)d_out;
    unfold_kernel<<<NTHREADS_ / 512, 512>>>(x, out);
}

// round 15
// speedup vs baseline: 1.0063x; 1.0063x over previous
#include <cuda_runtime.h>

// Unfold (im2col): x[16,96,56,56] f32, 3x3 window, pad 1
// out[(bc*9 + ki*3+kj)*3136 + h*56+w] = x_pad[bc][h+ki][w+kj]
//
// FINAL -- 30.72us best, verified 6x across independent runs and two launch
// geometries (jitter band 30.7-30.9). This is the HBM write wall:
// 173MB output / 30.72us = 5.63 TB/s sustained write-only, with the 19MB
// input (9x reuse) held L2-resident by evict-first (.cs) stores.
//
// Per thread (one (bc, h, w4) position): for each row r in {h-1,h,h+1}:
// 1 aligned LDG.128 + 2 predicated edge scalars, then 3 streaming STG.128
// built from the 6 staged values; a phase fence between rows keeps the
// front-batched-load count low. regs=30.
//
// Exhausted lever classes (all timed, all lose or tie):
//   mapping 1x4/9x4/36x4 -> 9x4 wins;  STG.256 36.9us;  TMA bulk 36.9us;
//   .wb policy 35.7us;  shuffle halos tie;  occ 30-80% no effect;
//   block 256/512 no effect.  No on-chip pipe >63% in any variant.

#define B_ 16
#define C_ 96
#define H_ 56
#define W_ 56
#define HW_ (H_ * W_)        // 3136
#define HW4_ (HW_ / 4)       // 784
#define NTHREADS_ (B_ * C_ * HW4_)   // 1,204,224 = 2352 * 512 exactly

__global__ __launch_bounds__(512) void unfold_kernel(
    const float* __restrict__ x, float* __restrict__ out)
{
    int tid = blockIdx.x * 512 + threadIdx.x;   // grid is exact, no guard

    int p4 = tid % HW4_;
    int bc = tid / HW4_;
    int p  = p4 * 4;
    int h  = p / W_;
    int w  = p - h * W_;      // multiple of 4

    const float* base  = x   + (size_t)bc * HW_;
    float*       obase = out + (size_t)bc * 9 * HW_ + p;

    #pragma unroll
    for (int r = 0; r < 3; r++) {
        int sh = h + r - 1;
        float v0, v1, v2, v3, v4, v5;   // [w-1, w, w+1, w+2, w+3, w+4]
        if (sh >= 0 && sh < H_) {
            const float* rp = base + sh * W_;
            float4 m = *reinterpret_cast<const float4*>(rp + w);   // aligned LDG.128
            v1 = m.x; v2 = m.y; v3 = m.z; v4 = m.w;
            v0 = (w > 0)      ? __ldg(rp + w - 1) : 0.f;
            v5 = (w + 4 < W_) ? __ldg(rp + w + 4) : 0.f;
        } else {
            v0 = v1 = v2 = v3 = v4 = v5 = 0.f;
        }

        float* o = obase + (size_t)(r * 3) * HW_;
        __stcs(reinterpret_cast<float4*>(o),           make_float4(v0, v1, v2, v3));
        __stcs(reinterpret_cast<float4*>(o + HW_),     make_float4(v1, v2, v3, v4));
        __stcs(reinterpret_cast<float4*>(o + 2 * HW_), make_float4(v2, v3, v4, v5));

        // phase fence: keep next row's loads below these stores
        asm volatile("" ::: "memory");
    }
}

extern "C" void kernel_launch(void* const* d_in, const int* in_sizes, int n_in,
                              void* d_out, int out_size)
{
    const float* x = (const float*)d_in[0];
    float* out = (float*)d_out;
    unfold_kernel<<<NTHREADS_ / 512, 512>>>(x, out);
}